// round 10
// baseline (speedup 1.0000x reference)
#include <cuda_runtime.h>
#include <math.h>

#define NBAGS 65536
#define EPSF 1e-7f
#define LN2F 0.69314718055994531f

#define FIX_SCALE 4194304.0f          /* 2^22 */
#define INV_FIX   2.38418579e-7f      /* 2^-22 */
#define MASK44    ((1ULL << 44) - 1)
#define MASK54    ((1ULL << 54) - 1)

// packed word per bag:
//   [0:44)  pos sum of log2(1-p+eps), fixed point 2^-22, mod 2^44 (two's-comp)
//   [44:54) pos count (+borrow; tested nonzero together with sum)
//   [54:64) neg count (presence)
// Zero-initialized at module load; mil_bag_final_kernel re-zeroes after each use.
__device__ unsigned long long g_packed[NBAGS];
// 0: neg_sum_log2, 1: num_neg_bags, 2: num_pos_bags, 3: pos_per_bag_sum
__device__ float        g_accum[4];
__device__ unsigned int g_done;

__device__ __forceinline__ void mil_process(float p, int l, int b, float& local2) {
    float t = fmaf(p, -1.0f, 1.0f + EPSF);           // 1 - p + eps
    float lg = __log2f(t);
    bool is_neg = (l == 0);
    int fx = __float2int_rn(lg * FIX_SCALE);         // >= -9.8e7, fits i32
    unsigned long long add = is_neg
        ? (1ULL << 54)
        : ((1ULL << 44) + ((unsigned long long)(long long)fx & MASK44));
    atomicAdd(&g_packed[b], add);                    // no return -> RED.64
    local2 += is_neg ? lg : 0.0f;
}

__global__ void __launch_bounds__(256) mil_main_kernel(
        const float4* __restrict__ p4,
        const int4* __restrict__ l4,
        const int4* __restrict__ b4,
        int n4, int n_total,
        const float* __restrict__ p_s,
        const int* __restrict__ l_s,
        const int* __restrict__ b_s) {
    int stride = gridDim.x * blockDim.x;
    float local2 = 0.0f;     // sum of log2(1-p+eps) over negatives

    for (int i = blockIdx.x * blockDim.x + threadIdx.x; i < n4; i += stride) {
        float4 p = __ldcs(p4 + i);     // streaming: evict-first
        int4   l = __ldcs(l4 + i);
        int4   b = __ldcs(b4 + i);
        mil_process(p.x, l.x, b.x, local2);
        mil_process(p.y, l.y, b.y, local2);
        mil_process(p.z, l.z, b.z, local2);
        mil_process(p.w, l.w, b.w, local2);
    }
    // scalar tail (N % 4 != 0)
    for (int j = n4 * 4 + blockIdx.x * blockDim.x + threadIdx.x;
         j < n_total; j += stride) {
        mil_process(p_s[j], l_s[j], b_s[j], local2);
    }

    // block reduction of local neg log2-sum -> 1 atomic per block
    __shared__ float warp_sums[8];
    int lane = threadIdx.x & 31;
    int wid  = threadIdx.x >> 5;
    #pragma unroll
    for (int off = 16; off > 0; off >>= 1)
        local2 += __shfl_down_sync(0xFFFFFFFFu, local2, off);
    if (lane == 0) warp_sums[wid] = local2;
    __syncthreads();
    if (wid == 0) {
        float v = (lane < 8) ? warp_sums[lane] : 0.0f;
        #pragma unroll
        for (int off = 4; off > 0; off >>= 1)
            v += __shfl_down_sync(0xFFFFFFFFu, v, off);
        if (lane == 0) atomicAdd(&g_accum[0], v);
    }
}

__device__ __forceinline__ void decode_word(unsigned long long W,
                                            float& nneg, float& npos, float& psum) {
    if ((unsigned int)(W >> 54)) nneg += 1.0f;
    unsigned long long pos_part = W & MASK54;
    if (pos_part != 0ULL) {
        npos += 1.0f;
        unsigned long long low44 = pos_part & MASK44;
        long long s_fixed = (low44 >= (1ULL << 43))
            ? (long long)low44 - (1LL << 44)
            : (long long)low44;
        float seg2 = (float)s_fixed * INV_FIX;       // log2 domain
        float v = fminf(exp2f(seg2), 1.0f);
        psum += __logf(1.0f - v + EPSF);
    }
}

// bag decode (4 bags/thread, MLP=2) + self-clean + (last block) final + reset
__global__ void __launch_bounds__(256) mil_bag_final_kernel(float* out) {
    int tid = threadIdx.x;
    // 64 blocks x 256 threads x 2 ulonglong2 = 65536 bags
    int idx0 = (blockIdx.x * 256 + tid);                 // first ulonglong2
    int idx1 = idx0 + 64 * 256;                          // second ulonglong2
    const ulonglong2* gp2 = (const ulonglong2*)g_packed;
    ulonglong2* gp2w = (ulonglong2*)g_packed;

    ulonglong2 w0 = gp2[idx0];
    ulonglong2 w1 = gp2[idx1];
    gp2w[idx0] = make_ulonglong2(0ULL, 0ULL);            // re-zero for next replay
    gp2w[idx1] = make_ulonglong2(0ULL, 0ULL);

    float nneg = 0.0f, npos = 0.0f, psum = 0.0f;
    decode_word(w0.x, nneg, npos, psum);
    decode_word(w0.y, nneg, npos, psum);
    decode_word(w1.x, nneg, npos, psum);
    decode_word(w1.y, nneg, npos, psum);

    __shared__ float sh[3][8];
    int lane = tid & 31, wid = tid >> 5;
    #pragma unroll
    for (int off = 16; off > 0; off >>= 1) {
        nneg += __shfl_down_sync(0xFFFFFFFFu, nneg, off);
        npos += __shfl_down_sync(0xFFFFFFFFu, npos, off);
        psum += __shfl_down_sync(0xFFFFFFFFu, psum, off);
    }
    if (lane == 0) { sh[0][wid] = nneg; sh[1][wid] = npos; sh[2][wid] = psum; }
    __syncthreads();
    bool last = false;
    if (wid == 0) {
        float a = (lane < 8) ? sh[0][lane] : 0.0f;
        float b = (lane < 8) ? sh[1][lane] : 0.0f;
        float c = (lane < 8) ? sh[2][lane] : 0.0f;
        #pragma unroll
        for (int off = 4; off > 0; off >>= 1) {
            a += __shfl_down_sync(0xFFFFFFFFu, a, off);
            b += __shfl_down_sync(0xFFFFFFFFu, b, off);
            c += __shfl_down_sync(0xFFFFFFFFu, c, off);
        }
        if (lane == 0) {
            atomicAdd(&g_accum[1], a);
            atomicAdd(&g_accum[2], b);
            atomicAdd(&g_accum[3], c);
            __threadfence();
            unsigned int t = atomicAdd(&g_done, 1u);
            last = (t == gridDim.x - 1);
        }
    }
    if (last) {
        float neg_sum = g_accum[0] * LN2F;   // log2 -> ln
        float nn = g_accum[1], np = g_accum[2], ps = g_accum[3];
        float neg_loss = (nn > 0.0f) ? (-neg_sum / fmaxf(nn, 1.0f)) : 0.0f;
        float pos_loss = (np > 0.0f) ? (-ps      / fmaxf(np, 1.0f)) : 0.0f;
        out[0] = neg_loss + pos_loss;
        // reset accumulator state for the next graph replay
        g_accum[0] = 0.0f; g_accum[1] = 0.0f;
        g_accum[2] = 0.0f; g_accum[3] = 0.0f;
        g_done = 0u;
    }
}

extern "C" void kernel_launch(void* const* d_in, const int* in_sizes, int n_in,
                              void* d_out, int out_size) {
    const float* probas  = (const float*)d_in[0];
    const int*   labels  = (const int*)d_in[1];
    const int*   bag_ids = (const int*)d_in[2];
    float*       out     = (float*)d_out;
    int n  = in_sizes[0];
    int n4 = n >> 2;

    int blocks = (n4 + 255) / 256;
    const int max_blocks = 148 * 16;
    if (blocks > max_blocks) blocks = max_blocks;
    if (blocks < 1) blocks = 1;
    mil_main_kernel<<<blocks, 256>>>((const float4*)probas, (const int4*)labels,
                                     (const int4*)bag_ids, n4, n,
                                     probas, labels, bag_ids);

    mil_bag_final_kernel<<<64, 256>>>(out);
}

// round 11
// speedup vs baseline: 1.0283x; 1.0283x over previous
#include <cuda_runtime.h>
#include <math.h>

#define NBAGS 65536
#define EPSF 1e-7f
#define LN2F 0.69314718055994531f

#define FIX_SCALE 4194304.0f          /* 2^22 */
#define INV_FIX   2.38418579e-7f      /* 2^-22 */
#define MASK44    ((1ULL << 44) - 1)
#define MASK54    ((1ULL << 54) - 1)

// packed word per bag:
//   [0:44)  pos sum of log2(1-p+eps), fixed point 2^-22, mod 2^44 (two's-comp)
//   [44:54) pos count (+borrow; tested nonzero together with sum)
//   [54:64) neg count (presence)
// Zero-initialized at module load; mil_bag_final_kernel re-zeroes after each use.
__device__ unsigned long long g_packed[NBAGS];
// 0: neg_sum_log2, 1: num_neg_bags, 2: num_pos_bags, 3: pos_per_bag_sum
__device__ float        g_accum[4];
__device__ unsigned int g_done;

__device__ __forceinline__ void mil_process(float p, int l, int b, float& local2) {
    float t = fmaf(p, -1.0f, 1.0f + EPSF);           // 1 - p + eps
    float lg = __log2f(t);
    bool is_neg = (l == 0);
    int fx = __float2int_rn(lg * FIX_SCALE);         // >= -9.8e7, fits i32
    unsigned long long add = is_neg
        ? (1ULL << 54)
        : ((1ULL << 44) + ((unsigned long long)(long long)fx & MASK44));
    atomicAdd(&g_packed[b], add);                    // no return -> RED.64
    local2 += is_neg ? lg : 0.0f;
}

__global__ void __launch_bounds__(256) mil_main_kernel(
        const float4* __restrict__ p4,
        const int4* __restrict__ l4,
        const int4* __restrict__ b4,
        int n4, int n_total,
        const float* __restrict__ p_s,
        const int* __restrict__ l_s,
        const int* __restrict__ b_s) {
    int stride = gridDim.x * blockDim.x;
    float local2 = 0.0f;     // sum of log2(1-p+eps) over negatives

    for (int i = blockIdx.x * blockDim.x + threadIdx.x; i < n4; i += stride) {
        float4 p = __ldcs(p4 + i);     // streaming: evict-first
        int4   l = __ldcs(l4 + i);
        int4   b = __ldcs(b4 + i);
        mil_process(p.x, l.x, b.x, local2);
        mil_process(p.y, l.y, b.y, local2);
        mil_process(p.z, l.z, b.z, local2);
        mil_process(p.w, l.w, b.w, local2);
    }
    // scalar tail (N % 4 != 0)
    for (int j = n4 * 4 + blockIdx.x * blockDim.x + threadIdx.x;
         j < n_total; j += stride) {
        mil_process(p_s[j], l_s[j], b_s[j], local2);
    }

    // block reduction of local neg log2-sum -> 1 atomic per block
    __shared__ float warp_sums[8];
    int lane = threadIdx.x & 31;
    int wid  = threadIdx.x >> 5;
    #pragma unroll
    for (int off = 16; off > 0; off >>= 1)
        local2 += __shfl_down_sync(0xFFFFFFFFu, local2, off);
    if (lane == 0) warp_sums[wid] = local2;
    __syncthreads();
    if (wid == 0) {
        float v = (lane < 8) ? warp_sums[lane] : 0.0f;
        #pragma unroll
        for (int off = 4; off > 0; off >>= 1)
            v += __shfl_down_sync(0xFFFFFFFFu, v, off);
        if (lane == 0) atomicAdd(&g_accum[0], v);
    }
}

__device__ __forceinline__ void decode_word(unsigned long long W,
                                            float& nneg, float& npos, float& psum) {
    if ((unsigned int)(W >> 54)) nneg += 1.0f;
    unsigned long long pos_part = W & MASK54;
    if (pos_part != 0ULL) {
        npos += 1.0f;
        unsigned long long low44 = pos_part & MASK44;
        long long s_fixed = (low44 >= (1ULL << 43))
            ? (long long)low44 - (1LL << 44)
            : (long long)low44;
        float seg2 = (float)s_fixed * INV_FIX;       // log2 domain
        float v = fminf(exp2f(seg2), 1.0f);
        psum += __logf(1.0f - v + EPSF);
    }
}

// bag decode (4 bags/thread, MLP=2) + self-clean + (last block) final + reset
// Launched with PDL: ramps up while mil_main is still running, then syncs.
__global__ void __launch_bounds__(256) mil_bag_final_kernel(float* out) {
    int tid = threadIdx.x;
    int idx0 = (blockIdx.x * 256 + tid);                 // first ulonglong2
    int idx1 = idx0 + 64 * 256;                          // second ulonglong2

    // Wait for mil_main_kernel's grid to complete (PDL dependency sync).
    cudaGridDependencySynchronize();

    const ulonglong2* gp2 = (const ulonglong2*)g_packed;
    ulonglong2* gp2w = (ulonglong2*)g_packed;

    ulonglong2 w0 = gp2[idx0];
    ulonglong2 w1 = gp2[idx1];
    gp2w[idx0] = make_ulonglong2(0ULL, 0ULL);            // re-zero for next replay
    gp2w[idx1] = make_ulonglong2(0ULL, 0ULL);

    float nneg = 0.0f, npos = 0.0f, psum = 0.0f;
    decode_word(w0.x, nneg, npos, psum);
    decode_word(w0.y, nneg, npos, psum);
    decode_word(w1.x, nneg, npos, psum);
    decode_word(w1.y, nneg, npos, psum);

    __shared__ float sh[3][8];
    int lane = tid & 31, wid = tid >> 5;
    #pragma unroll
    for (int off = 16; off > 0; off >>= 1) {
        nneg += __shfl_down_sync(0xFFFFFFFFu, nneg, off);
        npos += __shfl_down_sync(0xFFFFFFFFu, npos, off);
        psum += __shfl_down_sync(0xFFFFFFFFu, psum, off);
    }
    if (lane == 0) { sh[0][wid] = nneg; sh[1][wid] = npos; sh[2][wid] = psum; }
    __syncthreads();
    bool last = false;
    if (wid == 0) {
        float a = (lane < 8) ? sh[0][lane] : 0.0f;
        float b = (lane < 8) ? sh[1][lane] : 0.0f;
        float c = (lane < 8) ? sh[2][lane] : 0.0f;
        #pragma unroll
        for (int off = 4; off > 0; off >>= 1) {
            a += __shfl_down_sync(0xFFFFFFFFu, a, off);
            b += __shfl_down_sync(0xFFFFFFFFu, b, off);
            c += __shfl_down_sync(0xFFFFFFFFu, c, off);
        }
        if (lane == 0) {
            atomicAdd(&g_accum[1], a);
            atomicAdd(&g_accum[2], b);
            atomicAdd(&g_accum[3], c);
            __threadfence();
            unsigned int t = atomicAdd(&g_done, 1u);
            last = (t == gridDim.x - 1);
        }
    }
    if (last) {
        float neg_sum = g_accum[0] * LN2F;   // log2 -> ln
        float nn = g_accum[1], np = g_accum[2], ps = g_accum[3];
        float neg_loss = (nn > 0.0f) ? (-neg_sum / fmaxf(nn, 1.0f)) : 0.0f;
        float pos_loss = (np > 0.0f) ? (-ps      / fmaxf(np, 1.0f)) : 0.0f;
        out[0] = neg_loss + pos_loss;
        // reset accumulator state for the next graph replay
        g_accum[0] = 0.0f; g_accum[1] = 0.0f;
        g_accum[2] = 0.0f; g_accum[3] = 0.0f;
        g_done = 0u;
    }
}

extern "C" void kernel_launch(void* const* d_in, const int* in_sizes, int n_in,
                              void* d_out, int out_size) {
    const float* probas  = (const float*)d_in[0];
    const int*   labels  = (const int*)d_in[1];
    const int*   bag_ids = (const int*)d_in[2];
    float*       out     = (float*)d_out;
    int n  = in_sizes[0];
    int n4 = n >> 2;

    int blocks = (n4 + 255) / 256;
    const int max_blocks = 148 * 16;
    if (blocks > max_blocks) blocks = max_blocks;
    if (blocks < 1) blocks = 1;
    mil_main_kernel<<<blocks, 256>>>((const float4*)probas, (const int4*)labels,
                                     (const int4*)bag_ids, n4, n,
                                     probas, labels, bag_ids);

    // PDL launch: bag_final ramps while main runs, syncs via grid dependency.
    cudaLaunchConfig_t cfg = {};
    cfg.gridDim  = dim3(64, 1, 1);
    cfg.blockDim = dim3(256, 1, 1);
    cfg.dynamicSmemBytes = 0;
    cudaLaunchAttribute attrs[1];
    attrs[0].id = cudaLaunchAttributeProgrammaticStreamSerialization;
    attrs[0].val.programmaticStreamSerializationAllowed = 1;
    cfg.attrs = attrs;
    cfg.numAttrs = 1;
    cudaLaunchKernelEx(&cfg, mil_bag_final_kernel, out);
}